// round 2
// baseline (speedup 1.0000x reference)
#include <cuda_runtime.h>

#define NB   32
#define NE   8
#define CIN  64
#define COUT 64
#define HWP  25600   // 160*160
#define TP   128     // pixels per tile

// Mixed per-sample weights, stored TRANSPOSED as [b][i][o] so the GEMM
// kernel can copy straight into k-major shared memory.
__device__ float g_W[NB * CIN * COUT];

__global__ void mix_weights_kernel(const float* __restrict__ alpha,
                                   const float* __restrict__ ke) {
    int b = blockIdx.x;
    float a[NE];
#pragma unroll
    for (int e = 0; e < NE; e++) a[e] = alpha[b * NE + e];
    for (int idx = threadIdx.x; idx < COUT * CIN; idx += blockDim.x) {
        int o = idx / CIN;
        int i = idx % CIN;
        float s = 0.f;
#pragma unroll
        for (int e = 0; e < NE; e++) s += a[e] * ke[e * COUT * CIN + idx];
        g_W[b * CIN * COUT + i * COUT + o] = s;   // transposed [i][o]
    }
}

// One CTA: 64 Cout x 128 pixels, K=64 fully resident in smem.
// 256 threads, each computes an 8(o) x 4(p) register tile.
__global__ __launch_bounds__(256)
void conv_kernel(const float* __restrict__ x, float* __restrict__ out) {
    __shared__ float w_s[CIN * COUT];  // [k][o], 16 KB
    __shared__ float x_s[CIN * TP];    // [k][p], 32 KB

    const int tile = blockIdx.x;       // 0..199
    const int b    = blockIdx.y;       // 0..31
    const int tid  = threadIdx.x;

    // Load W_b (already transposed) into smem, vectorized.
    {
        const float4* wsrc = (const float4*)(g_W + (size_t)b * CIN * COUT);
        float4* wdst = (float4*)w_s;
#pragma unroll
        for (int idx = tid; idx < CIN * COUT / 4; idx += 256) wdst[idx] = wsrc[idx];
    }

    // Load X tile [64 k x 128 p], vectorized & coalesced (512B rows).
    {
        const float* xb = x + (size_t)b * CIN * HWP + (size_t)tile * TP;
#pragma unroll
        for (int idx = tid; idx < CIN * (TP / 4); idx += 256) {
            int row = idx / (TP / 4);
            int c   = idx % (TP / 4);
            *(float4*)&x_s[row * TP + c * 4] =
                *(const float4*)&xb[(size_t)row * HWP + c * 4];
        }
    }
    __syncthreads();

    const int warp = tid >> 5;
    const int lane = tid & 31;
    const int to = warp * 8;   // warp-uniform -> w_s reads are broadcast
    const int tp = lane * 4;   // lanes span 512B -> conflict-free LDS.128

    float acc[8][4];
#pragma unroll
    for (int i = 0; i < 8; i++)
#pragma unroll
        for (int j = 0; j < 4; j++) acc[i][j] = 0.f;

#pragma unroll 16
    for (int k = 0; k < CIN; k++) {
        float4 xv = *(const float4*)&x_s[k * TP + tp];
        float4 w0 = *(const float4*)&w_s[k * COUT + to];
        float4 w1 = *(const float4*)&w_s[k * COUT + to + 4];
        float wv[8] = {w0.x, w0.y, w0.z, w0.w, w1.x, w1.y, w1.z, w1.w};
#pragma unroll
        for (int i = 0; i < 8; i++) {
            acc[i][0] += wv[i] * xv.x;
            acc[i][1] += wv[i] * xv.y;
            acc[i][2] += wv[i] * xv.z;
            acc[i][3] += wv[i] * xv.w;
        }
    }

    // Store: float4 per (o,p-quad), coalesced across lanes.
    float* ob = out + (size_t)b * COUT * HWP + (size_t)tile * TP;
#pragma unroll
    for (int i = 0; i < 8; i++) {
        *(float4*)&ob[(size_t)(to + i) * HWP + tp] =
            make_float4(acc[i][0], acc[i][1], acc[i][2], acc[i][3]);
    }
}

extern "C" void kernel_launch(void* const* d_in, const int* in_sizes, int n_in,
                              void* d_out, int out_size) {
    const float* x     = (const float*)d_in[0];  // [32,64,160,160]
    const float* alpha = (const float*)d_in[1];  // [32,8]
    const float* ke    = (const float*)d_in[2];  // [8,64,64,1,1]
    float* out = (float*)d_out;                  // [32,64,160,160]

    mix_weights_kernel<<<NB, 256>>>(alpha, ke);
    conv_kernel<<<dim3(HWP / TP, NB), 256>>>(x, out);
}

// round 7
// speedup vs baseline: 1.0659x; 1.0659x over previous
#include <cuda_runtime.h>
#include <cstdint>

#define NB   32
#define NE   8
#define CIN  64
#define COUT 64
#define HWP  25600   // 160*160
#define TP   256     // pixels per CTA tile

typedef unsigned long long ull;

// Mixed per-sample weights, TRANSPOSED [b][i][o].
__device__ float g_W[NB * CIN * COUT];

__global__ void mix_weights_kernel(const float* __restrict__ alpha,
                                   const float* __restrict__ ke) {
    int b = blockIdx.x;
    int q = blockIdx.y;          // quarter of the 4096 entries
    float a[NE];
#pragma unroll
    for (int e = 0; e < NE; e++) a[e] = alpha[b * NE + e];
    int base = q * (COUT * CIN / 4);
#pragma unroll
    for (int t = 0; t < (COUT * CIN / 4) / 256; t++) {
        int idx = base + t * 256 + threadIdx.x;
        int o = idx / CIN;
        int i = idx % CIN;
        float s = 0.f;
#pragma unroll
        for (int e = 0; e < NE; e++) s += a[e] * ke[e * COUT * CIN + idx];
        g_W[b * CIN * COUT + i * COUT + o] = s;   // transposed [i][o]
    }
}

__device__ __forceinline__ void ffma2(ull& d, ull a, ull b) {
    asm("fma.rn.f32x2 %0, %1, %2, %0;" : "+l"(d) : "l"(a), "l"(b));
}
__device__ __forceinline__ ull pack2(float w) {
    unsigned u = __float_as_uint(w);
    ull r;
    asm("mov.b64 %0, {%1, %1};" : "=l"(r) : "r"(u));
    return r;
}

// One CTA: 64 Cout x 256 pixels, K=64 resident in smem.
// 256 threads, each computes an 8(o) x 8(p) register tile via f32x2 FMA.
__global__ __launch_bounds__(256)
void conv_kernel(const float* __restrict__ x, float* __restrict__ out) {
    __shared__ float w_s[CIN * COUT];       // [k][o], 16 KB (static)
    extern __shared__ float x_s[];          // [k][p], 64 KB (dynamic)

    const int tile = blockIdx.x;            // 0..99
    const int b    = blockIdx.y;            // 0..31
    const int tid  = threadIdx.x;

    // W_b (transposed) -> smem, vectorized.
    {
        const float4* wsrc = (const float4*)(g_W + (size_t)b * CIN * COUT);
        float4* wdst = (float4*)w_s;
#pragma unroll
        for (int idx = tid; idx < CIN * COUT / 4; idx += 256) wdst[idx] = wsrc[idx];
    }
    // X tile [64 k x 256 p], coalesced float4 (1KB rows).
    {
        const float* xb = x + (size_t)b * CIN * HWP + (size_t)tile * TP;
#pragma unroll
        for (int idx = tid; idx < CIN * (TP / 4); idx += 256) {
            int row = idx / (TP / 4);
            int c   = idx % (TP / 4);
            *(float4*)&x_s[row * TP + c * 4] =
                *(const float4*)&xb[(size_t)row * HWP + c * 4];
        }
    }
    __syncthreads();

    const int warp = tid >> 5;
    const int lane = tid & 31;
    const int to = warp * 8;     // warp-uniform -> broadcast LDS for w
    const int tp = lane * 4;     // 16B stride -> conflict-free LDS.128

    ull acc[8][4];
#pragma unroll
    for (int i = 0; i < 8; i++)
#pragma unroll
        for (int j = 0; j < 4; j++) acc[i][j] = 0ull;

#pragma unroll 8
    for (int k = 0; k < CIN; k++) {
        const float4 w0 = *(const float4*)&w_s[k * COUT + to];
        const float4 w1 = *(const float4*)&w_s[k * COUT + to + 4];
        ull wp[8];
        wp[0] = pack2(w0.x); wp[1] = pack2(w0.y);
        wp[2] = pack2(w0.z); wp[3] = pack2(w0.w);
        wp[4] = pack2(w1.x); wp[5] = pack2(w1.y);
        wp[6] = pack2(w1.z); wp[7] = pack2(w1.w);

        const ulonglong2 xa = *(const ulonglong2*)&x_s[k * TP + tp];
        const ulonglong2 xb = *(const ulonglong2*)&x_s[k * TP + tp + 128];
#pragma unroll
        for (int i = 0; i < 8; i++) {
            ffma2(acc[i][0], wp[i], xa.x);
            ffma2(acc[i][1], wp[i], xa.y);
            ffma2(acc[i][2], wp[i], xb.x);
            ffma2(acc[i][3], wp[i], xb.y);
        }
    }

    // Stores: 16B per (o, p-quad), coalesced across lanes.
    float* ob = out + (size_t)b * COUT * HWP + (size_t)tile * TP;
#pragma unroll
    for (int i = 0; i < 8; i++) {
        ulonglong2 v0; v0.x = acc[i][0]; v0.y = acc[i][1];
        ulonglong2 v1; v1.x = acc[i][2]; v1.y = acc[i][3];
        *(ulonglong2*)&ob[(size_t)(to + i) * HWP + tp]       = v0;
        *(ulonglong2*)&ob[(size_t)(to + i) * HWP + tp + 128] = v1;
    }
}

extern "C" void kernel_launch(void* const* d_in, const int* in_sizes, int n_in,
                              void* d_out, int out_size) {
    const float* x     = (const float*)d_in[0];  // [32,64,160,160]
    const float* alpha = (const float*)d_in[1];  // [32,8]
    const float* ke    = (const float*)d_in[2];  // [8,64,64,1,1]
    float* out = (float*)d_out;                  // [32,64,160,160]

    static bool attr_set = false;
    if (!attr_set) {
        cudaFuncSetAttribute(conv_kernel,
                             cudaFuncAttributeMaxDynamicSharedMemorySize,
                             CIN * TP * (int)sizeof(float));
        attr_set = true;
    }

    mix_weights_kernel<<<dim3(NB, 4), 256>>>(alpha, ke);
    conv_kernel<<<dim3(HWP / TP, NB), 256, CIN * TP * sizeof(float)>>>(x, out);
}